// round 3
// baseline (speedup 1.0000x reference)
#include <cuda_runtime.h>
#include <cuda_bf16.h>
#include <math.h>

#define NMAX    50000
#define DMODEL  128
#define ALPHA   0.2f
#define LN_EPS  1e-5f

// ---------------- scratch (device globals; no allocations allowed) ----------
__device__ __align__(16) __nv_bfloat16 g_Qh[NMAX * DMODEL];
__device__ __align__(16) __nv_bfloat16 g_Kh[NMAX * DMODEL];
__device__ __align__(16) __nv_bfloat16 g_Vh[NMAX * DMODEL];
__device__ __align__(16) float g_AGG[NMAX * DMODEL];
__device__ __align__(16) float g_ew[800000 + 64];
__device__ __align__(16) int   g_row[800000 + 64];
__device__ __align__(16) int   g_col[800000 + 64];
__device__ int g_is64;

// ---------------- packed f32x2 helpers --------------------------------------
__device__ __forceinline__ unsigned long long pk2(float lo, float hi)
{
    unsigned long long r;
    asm("mov.b64 %0, {%1, %2};" : "=l"(r) : "f"(lo), "f"(hi));
    return r;
}
__device__ __forceinline__ void upk2(unsigned long long v, float& lo, float& hi)
{
    asm("mov.b64 {%0, %1}, %2;" : "=f"(lo), "=f"(hi) : "l"(v));
}
__device__ __forceinline__ void ffma2(unsigned long long& d,
                                      unsigned long long a,
                                      unsigned long long b)
{
    asm("fma.rn.f32x2 %0, %1, %2, %0;" : "+l"(d) : "l"(a), "l"(b));
}

// ---------------- detect edge_index dtype (int32 vs int64) ------------------
__global__ void detect_kernel(const unsigned* __restrict__ ei, int E)
{
    if (blockIdx.x == 0 && threadIdx.x == 0) {
        int is64 = 1;
        int m = (E >= 64) ? 64 : E;
        for (int i = 0; i < m; i++) {
            if (ei[2 * i + 1] != 0u) { is64 = 0; break; }
        }
        g_is64 = is64;
    }
}

// ---------------- prep: int32 indices + edge gate ----------------------------
__global__ void prep_kernel(const void* __restrict__ eiv,
                            const float* __restrict__ eattr,
                            int E)
{
    int e = blockIdx.x * blockDim.x + threadIdx.x;
    if (e >= E) return;

    int row, col;
    if (g_is64) {
        const long long* p = reinterpret_cast<const long long*>(eiv);
        row = (int)p[e];
        col = (int)p[(long long)E + e];
    } else {
        const int* p = reinterpret_cast<const int*>(eiv);
        row = p[e];
        col = p[E + e];
    }
    g_row[e] = row;
    g_col[e] = col;

    const float4* a4 = reinterpret_cast<const float4*>(eattr) + (size_t)e * 4;
    float s = 0.f;
#pragma unroll
    for (int i = 0; i < 4; i++) {
        float4 a = a4[i];
        s += a.x + a.y + a.z + a.w;
    }
    g_ew[e] = 1.f / (1.f + __expf(-s));
}

// ---------------- zero the aggregation buffer -------------------------------
__global__ void zero_kernel(int n4)
{
    float4 z = make_float4(0.f, 0.f, 0.f, 0.f);
    float4* p = reinterpret_cast<float4*>(g_AGG);
    for (int i = blockIdx.x * blockDim.x + threadIdx.x; i < n4;
         i += gridDim.x * blockDim.x)
        p[i] = z;
}

// ---------------- fused QKV projection GEMM (fp32 math, bf16 output) --------
// One block = 128 rows of x (smem, loaded once), loops over Wq/Wk/Wv.
// 256 threads; thread tile 8x8, cols j = tx + 16*v (conflict-free b reads).
// FMAs as packed f32x2 pairing accumulator rows. Epilogue stages fp32 result
// back into the ws tile, then does coalesced bf16x2 stores.
#define QKV_SMEM (2 * 128 * 129 * 4)

__global__ void __launch_bounds__(256, 1)
qkv_kernel(const float* __restrict__ x,
           const float* __restrict__ Wq,
           const float* __restrict__ Wk,
           const float* __restrict__ Wv,
           int n)
{
    extern __shared__ float sm[];
    float* xs = sm;              // [128][129]
    float* ws = sm + 128 * 129;  // [128][129] (weights, then result staging)

    const int row0 = blockIdx.x * 128;
    const int tid  = threadIdx.x;
    const int ty   = tid >> 4;   // 0..15
    const int tx   = tid & 15;   // 0..15
    const int i0   = ty * 8;

    // load x tile once
    for (int t = tid; t < 128 * 32; t += 256) {
        int r  = t >> 5;
        int c4 = t & 31;
        float4 v = make_float4(0.f, 0.f, 0.f, 0.f);
        int gr = row0 + r;
        if (gr < n) v = reinterpret_cast<const float4*>(x)[gr * 32 + c4];
        float* d = xs + r * 129 + c4 * 4;
        d[0] = v.x; d[1] = v.y; d[2] = v.z; d[3] = v.w;
    }

    const float* Ws[3]   = {Wq, Wk, Wv};
    __nv_bfloat16* Os[3] = {g_Qh, g_Kh, g_Vh};

    for (int w = 0; w < 3; w++) {
        __syncthreads();   // xs ready / ws free from previous iteration
        const float* W = Ws[w];
        for (int t = tid; t < 128 * 32; t += 256) {
            int r  = t >> 5;
            int c4 = t & 31;
            float4 v = reinterpret_cast<const float4*>(W)[r * 32 + c4];
            float* d = ws + r * 129 + c4 * 4;
            d[0] = v.x; d[1] = v.y; d[2] = v.z; d[3] = v.w;
        }
        __syncthreads();

        unsigned long long acc2[4][8];
#pragma unroll
        for (int up = 0; up < 4; up++)
#pragma unroll
            for (int v = 0; v < 8; v++) acc2[up][v] = 0ull;

#pragma unroll 8
        for (int k = 0; k < 128; k++) {
            float a_[8], b_[8];
#pragma unroll
            for (int u = 0; u < 8; u++) a_[u] = xs[(i0 + u) * 129 + k];
#pragma unroll
            for (int v = 0; v < 8; v++) b_[v] = ws[(tx + 16 * v) * 129 + k];
            unsigned long long ap[4], bp[8];
#pragma unroll
            for (int up = 0; up < 4; up++) ap[up] = pk2(a_[2 * up], a_[2 * up + 1]);
#pragma unroll
            for (int v = 0; v < 8; v++) bp[v] = pk2(b_[v], b_[v]);
#pragma unroll
            for (int up = 0; up < 4; up++)
#pragma unroll
                for (int v = 0; v < 8; v++)
                    ffma2(acc2[up][v], ap[up], bp[v]);
        }

        const float scale = (w == 0) ? 0.25f : 1.0f;  // fold 1/sqrt(HD) into Q
        __syncthreads();                   // done reading ws
        // stage fp32 result into ws
#pragma unroll
        for (int up = 0; up < 4; up++)
#pragma unroll
            for (int v = 0; v < 8; v++) {
                float lo, hi;
                upk2(acc2[up][v], lo, hi);
                ws[(i0 + 2 * up + 0) * 129 + tx + 16 * v] = lo * scale;
                ws[(i0 + 2 * up + 1) * 129 + tx + 16 * v] = hi * scale;
            }
        __syncthreads();

        // coalesced bf16x2 stores
        __nv_bfloat162* OUT = reinterpret_cast<__nv_bfloat162*>(Os[w]);
        for (int t = tid; t < 128 * 64; t += 256) {
            int r = t >> 6;
            int c = t & 63;
            int gr = row0 + r;
            if (gr < n) {
                __nv_bfloat162 h = __floats2bfloat162_rn(ws[r * 129 + 2 * c],
                                                         ws[r * 129 + 2 * c + 1]);
                OUT[gr * 64 + c] = h;
            }
        }
    }
}

// ---------------- per-edge attention + scatter-add --------------------------
// One warp per edge. Lane l owns floats [4l..4l+3]; head h = l>>2.
__global__ void __launch_bounds__(256)
edge_kernel(int E)
{
    const int gw   = (blockIdx.x * blockDim.x + threadIdx.x) >> 5;
    const int lane = threadIdx.x & 31;
    if (gw >= E) return;

    const int row = __ldg(&g_row[gw]);
    const int col = __ldg(&g_col[gw]);
    float ew = __ldg(&g_ew[gw]);

    const uint2* Q2 = reinterpret_cast<const uint2*>(g_Qh);
    const uint2* K2 = reinterpret_cast<const uint2*>(g_Kh);
    const uint2* V2 = reinterpret_cast<const uint2*>(g_Vh);

    uint2 qu = Q2[row * 32 + lane];
    uint2 ku = K2[col * 32 + lane];
    uint2 vu = V2[row * 32 + lane];

    float2 q01 = __bfloat1622float2(*reinterpret_cast<__nv_bfloat162*>(&qu.x));
    float2 q23 = __bfloat1622float2(*reinterpret_cast<__nv_bfloat162*>(&qu.y));
    float2 k01 = __bfloat1622float2(*reinterpret_cast<__nv_bfloat162*>(&ku.x));
    float2 k23 = __bfloat1622float2(*reinterpret_cast<__nv_bfloat162*>(&ku.y));
    float2 v01 = __bfloat1622float2(*reinterpret_cast<__nv_bfloat162*>(&vu.x));
    float2 v23 = __bfloat1622float2(*reinterpret_cast<__nv_bfloat162*>(&vu.y));

    // per-head dot over HD=16 = 4 lanes x 4 floats (Q pre-scaled by 1/sqrt(HD))
    float s = q01.x * k01.x + q01.y * k01.y + q23.x * k23.x + q23.y * k23.y;
    s += __shfl_xor_sync(0xffffffffu, s, 1);
    s += __shfl_xor_sync(0xffffffffu, s, 2);
    // LeakyReLU, then edge gate
    s = (s > 0.f) ? s : ALPHA * s;
    s *= ew;

    // softmax across the 8 heads
    float m = s;
    m = fmaxf(m, __shfl_xor_sync(0xffffffffu, m, 4));
    m = fmaxf(m, __shfl_xor_sync(0xffffffffu, m, 8));
    m = fmaxf(m, __shfl_xor_sync(0xffffffffu, m, 16));
    float p = __expf(s - m);
    float den = p;
    den += __shfl_xor_sync(0xffffffffu, den, 4);
    den += __shfl_xor_sync(0xffffffffu, den, 8);
    den += __shfl_xor_sync(0xffffffffu, den, 16);
    p /= den;

    float* dst = g_AGG + col * DMODEL + lane * 4;
    asm volatile("red.global.add.v4.f32 [%0], {%1, %2, %3, %4};"
                 :: "l"(dst), "f"(p * v01.x), "f"(p * v01.y),
                    "f"(p * v23.x), "f"(p * v23.y)
                 : "memory");
}

// ---------------- output projection + residual + LayerNorm ------------------
#define OUT_SMEM ((2 * 128 * 129 + 128 * 132) * 4)

__global__ void __launch_bounds__(256, 1)
out_ln_kernel(const float* __restrict__ x,
              const float* __restrict__ Wo,
              const float* __restrict__ bo,
              const float* __restrict__ gamma,
              const float* __restrict__ beta,
              float* __restrict__ out,
              int n)
{
    extern __shared__ float sm[];
    float* as  = sm;                  // [128][129]  AGG tile
    float* ws  = sm + 128 * 129;      // [128][129]  Wo
    float* res = sm + 2 * 128 * 129;  // [128][132]  GEMM result staging

    const int row0 = blockIdx.x * 128;
    const int tid  = threadIdx.x;
    const int ty   = tid >> 4;
    const int tx   = tid & 15;
    const int i0   = ty * 8;

    for (int t = tid; t < 128 * 32; t += 256) {
        int r  = t >> 5;
        int c4 = t & 31;
        float4 v = make_float4(0.f, 0.f, 0.f, 0.f);
        int gr = row0 + r;
        if (gr < n) v = reinterpret_cast<const float4*>(g_AGG)[gr * 32 + c4];
        float* d = as + r * 129 + c4 * 4;
        d[0] = v.x; d[1] = v.y; d[2] = v.z; d[3] = v.w;
    }
    for (int t = tid; t < 128 * 32; t += 256) {
        int r  = t >> 5;
        int c4 = t & 31;
        float4 v = reinterpret_cast<const float4*>(Wo)[r * 32 + c4];
        float* d = ws + r * 129 + c4 * 4;
        d[0] = v.x; d[1] = v.y; d[2] = v.z; d[3] = v.w;
    }
    __syncthreads();

    unsigned long long acc2[4][8];
#pragma unroll
    for (int up = 0; up < 4; up++)
#pragma unroll
        for (int v = 0; v < 8; v++) acc2[up][v] = 0ull;

#pragma unroll 8
    for (int k = 0; k < 128; k++) {
        float a_[8], b_[8];
#pragma unroll
        for (int u = 0; u < 8; u++) a_[u] = as[(i0 + u) * 129 + k];
#pragma unroll
        for (int v = 0; v < 8; v++) b_[v] = ws[(tx + 16 * v) * 129 + k];
        unsigned long long ap[4], bp[8];
#pragma unroll
        for (int up = 0; up < 4; up++) ap[up] = pk2(a_[2 * up], a_[2 * up + 1]);
#pragma unroll
        for (int v = 0; v < 8; v++) bp[v] = pk2(b_[v], b_[v]);
#pragma unroll
        for (int up = 0; up < 4; up++)
#pragma unroll
            for (int v = 0; v < 8; v++)
                ffma2(acc2[up][v], ap[up], bp[v]);
    }

    // stage to smem
#pragma unroll
    for (int up = 0; up < 4; up++)
#pragma unroll
        for (int v = 0; v < 8; v++) {
            float lo, hi;
            upk2(acc2[up][v], lo, hi);
            res[(i0 + 2 * up + 0) * 132 + tx + 16 * v] = lo;
            res[(i0 + 2 * up + 1) * 132 + tx + 16 * v] = hi;
        }
    __syncthreads();

    // residual + LayerNorm: 8 warps x 16 rows each
    const int warp = tid >> 5;
    const int lane = tid & 31;
    float4 bo4 = reinterpret_cast<const float4*>(bo)[lane];
    float4 g4  = reinterpret_cast<const float4*>(gamma)[lane];
    float4 b4  = reinterpret_cast<const float4*>(beta)[lane];

    for (int r = warp; r < 128; r += 8) {
        int gr = row0 + r;
        if (gr >= n) continue;
        float4 a  = *reinterpret_cast<float4*>(res + r * 132 + lane * 4);
        float4 xv = reinterpret_cast<const float4*>(x)[gr * 32 + lane];
        float o0 = a.x + bo4.x + xv.x;
        float o1 = a.y + bo4.y + xv.y;
        float o2 = a.z + bo4.z + xv.z;
        float o3 = a.w + bo4.w + xv.w;

        float s  = o0 + o1 + o2 + o3;
        float ss = o0 * o0 + o1 * o1 + o2 * o2 + o3 * o3;
#pragma unroll
        for (int off = 16; off >= 1; off >>= 1) {
            s  += __shfl_xor_sync(0xffffffffu, s,  off);
            ss += __shfl_xor_sync(0xffffffffu, ss, off);
        }
        float mu  = s * (1.f / 128.f);
        float var = ss * (1.f / 128.f) - mu * mu;
        float inv = rsqrtf(var + LN_EPS);

        float4 o;
        o.x = (o0 - mu) * inv * g4.x + b4.x;
        o.y = (o1 - mu) * inv * g4.y + b4.y;
        o.z = (o2 - mu) * inv * g4.z + b4.z;
        o.w = (o3 - mu) * inv * g4.w + b4.w;
        reinterpret_cast<float4*>(out)[gr * 32 + lane] = o;
    }
}

// ---------------- launcher ---------------------------------------------------
extern "C" void kernel_launch(void* const* d_in, const int* in_sizes, int n_in,
                              void* d_out, int out_size)
{
    const float* x     = (const float*)d_in[0];
    const void*  ei    = d_in[1];
    const float* eattr = (const float*)d_in[2];
    const float* Wq    = (const float*)d_in[3];
    const float* Wk    = (const float*)d_in[4];
    const float* Wv    = (const float*)d_in[5];
    const float* Wo    = (const float*)d_in[6];
    const float* bo    = (const float*)d_in[7];
    const float* gamma = (const float*)d_in[8];
    const float* beta  = (const float*)d_in[9];
    float* out = (float*)d_out;

    int n = in_sizes[0] / DMODEL;
    int E = in_sizes[1] / 2;
    if (n > NMAX) n = NMAX;

    cudaFuncSetAttribute(qkv_kernel,
                         cudaFuncAttributeMaxDynamicSharedMemorySize, QKV_SMEM);
    cudaFuncSetAttribute(out_ln_kernel,
                         cudaFuncAttributeMaxDynamicSharedMemorySize, OUT_SMEM);

    detect_kernel<<<1, 32>>>((const unsigned*)ei, E);
    prep_kernel<<<(E + 255) / 256, 256>>>(ei, eattr, E);
    zero_kernel<<<512, 256>>>(n * 32);

    int nrb = (n + 127) / 128;
    qkv_kernel<<<nrb, 256, QKV_SMEM>>>(x, Wq, Wk, Wv, n);

    long long ethreads = (long long)E * 32;
    int eblocks = (int)((ethreads + 255) / 256);
    edge_kernel<<<eblocks, 256>>>(E);

    out_ln_kernel<<<nrb, 256, OUT_SMEM>>>(x, Wo, bo, gamma, beta, out, n);
}

// round 5
// speedup vs baseline: 1.4382x; 1.4382x over previous
#include <cuda_runtime.h>
#include <cuda_bf16.h>
#include <math.h>

#define NMAX    50000
#define DMODEL  128
#define ALPHA   0.2f
#define LN_EPS  1e-5f

// ---------------- scratch (device globals; no allocations allowed) ----------
__device__ __align__(16) __nv_bfloat16 g_Qh[NMAX * DMODEL];
__device__ __align__(16) __nv_bfloat16 g_Kh[NMAX * DMODEL];
__device__ __align__(16) __nv_bfloat16 g_Vh[NMAX * DMODEL];
__device__ __align__(16) float g_AGG[NMAX * DMODEL];
__device__ __align__(16) float g_ew[800000 + 64];
__device__ __align__(16) int   g_row[800000 + 64];
__device__ __align__(16) int   g_col[800000 + 64];
__device__ int g_is64;

// ---------------- tf32 mma helpers ------------------------------------------
__device__ __forceinline__ unsigned cvt_tf32(float f)
{
    unsigned u;
    asm("cvt.rna.tf32.f32 %0, %1;" : "=r"(u) : "f"(f));
    return u;
}

__device__ __forceinline__ void mma_tf32(float c[4],
                                         unsigned a0, unsigned a1,
                                         unsigned a2, unsigned a3,
                                         unsigned b0, unsigned b1)
{
    asm("mma.sync.aligned.m16n8k8.row.col.f32.tf32.tf32.f32 "
        "{%0,%1,%2,%3}, {%4,%5,%6,%7}, {%8,%9}, {%0,%1,%2,%3};"
        : "+f"(c[0]), "+f"(c[1]), "+f"(c[2]), "+f"(c[3])
        : "r"(a0), "r"(a1), "r"(a2), "r"(a3), "r"(b0), "r"(b1));
}

// ---------------- detect edge_index dtype (int32 vs int64) ------------------
__global__ void detect_kernel(const unsigned* __restrict__ ei, int E)
{
    if (blockIdx.x == 0 && threadIdx.x == 0) {
        int is64 = 1;
        int m = (E >= 64) ? 64 : E;
        for (int i = 0; i < m; i++) {
            if (ei[2 * i + 1] != 0u) { is64 = 0; break; }
        }
        g_is64 = is64;
    }
}

// ---------------- prep: int32 indices + edge gate ----------------------------
__global__ void prep_kernel(const void* __restrict__ eiv,
                            const float* __restrict__ eattr,
                            int E)
{
    int e = blockIdx.x * blockDim.x + threadIdx.x;
    if (e >= E) return;

    int row, col;
    if (g_is64) {
        const long long* p = reinterpret_cast<const long long*>(eiv);
        row = (int)p[e];
        col = (int)p[(long long)E + e];
    } else {
        const int* p = reinterpret_cast<const int*>(eiv);
        row = p[e];
        col = p[E + e];
    }
    g_row[e] = row;
    g_col[e] = col;

    const float4* a4 = reinterpret_cast<const float4*>(eattr) + (size_t)e * 4;
    float s = 0.f;
#pragma unroll
    for (int i = 0; i < 4; i++) {
        float4 a = a4[i];
        s += a.x + a.y + a.z + a.w;
    }
    g_ew[e] = 1.f / (1.f + __expf(-s));
}

// ---------------- zero the aggregation buffer -------------------------------
__global__ void zero_kernel(int n4)
{
    float4 z = make_float4(0.f, 0.f, 0.f, 0.f);
    float4* p = reinterpret_cast<float4*>(g_AGG);
    for (int i = blockIdx.x * blockDim.x + threadIdx.x; i < n4;
         i += gridDim.x * blockDim.x)
        p[i] = z;
}

// ---------------- fused QKV projection GEMM (tf32 MMA, bf16 out) ------------
// Block = 128 rows; x tile loaded once, loops over Wq/Wk/Wv.
// 8 warps as 4x2: warp covers 32 rows x 64 cols = 2x8 m16n8k8 tiles.
// Smem stride 132 => fragment gathers are bank-conflict-free (4g+tg mod 32).
#define QKV_SMEM (2 * 128 * 132 * 4)

__global__ void __launch_bounds__(256, 1)
qkv_kernel(const float* __restrict__ x,
           const float* __restrict__ Wq,
           const float* __restrict__ Wk,
           const float* __restrict__ Wv,
           int n)
{
    extern __shared__ float sm[];
    float* xs = sm;              // [128][132]
    float* ws = sm + 128 * 132;  // [128][132]

    const int row0 = blockIdx.x * 128;
    const int tid  = threadIdx.x;
    const int warp = tid >> 5;
    const int lane = tid & 31;
    const int g    = lane >> 2;   // 0..7
    const int tg   = lane & 3;    // 0..3
    const int wr   = warp & 3;    // row group: 32 rows
    const int wc   = warp >> 2;   // col group: 64 cols
    const int rb   = wr * 32;
    const int cb   = wc * 64;

    // load x tile once (zero-padded past n)
    for (int t = tid; t < 128 * 32; t += 256) {
        int r  = t >> 5;
        int c4 = t & 31;
        float4 v = make_float4(0.f, 0.f, 0.f, 0.f);
        int gr = row0 + r;
        if (gr < n) v = reinterpret_cast<const float4*>(x)[gr * 32 + c4];
        float* d = xs + r * 132 + c4 * 4;
        d[0] = v.x; d[1] = v.y; d[2] = v.z; d[3] = v.w;
    }

    const float* Ws[3]   = {Wq, Wk, Wv};
    __nv_bfloat16* Os[3] = {g_Qh, g_Kh, g_Vh};

    for (int w = 0; w < 3; w++) {
        __syncthreads();   // xs ready / previous iter done with ws
        const float* W = Ws[w];
        for (int t = tid; t < 128 * 32; t += 256) {
            int r  = t >> 5;
            int c4 = t & 31;
            float4 v = reinterpret_cast<const float4*>(W)[r * 32 + c4];
            float* d = ws + r * 132 + c4 * 4;
            d[0] = v.x; d[1] = v.y; d[2] = v.z; d[3] = v.w;
        }
        __syncthreads();

        float c[2][8][4];
#pragma unroll
        for (int mt = 0; mt < 2; mt++)
#pragma unroll
            for (int nt = 0; nt < 8; nt++)
#pragma unroll
                for (int i = 0; i < 4; i++) c[mt][nt][i] = 0.f;

#pragma unroll 4
        for (int kt = 0; kt < 16; kt++) {
            const int k0 = kt * 8;
            unsigned a[2][4];
#pragma unroll
            for (int mt = 0; mt < 2; mt++) {
                int r = rb + mt * 16 + g;
                a[mt][0] = cvt_tf32(xs[r * 132 + k0 + tg]);
                a[mt][1] = cvt_tf32(xs[(r + 8) * 132 + k0 + tg]);
                a[mt][2] = cvt_tf32(xs[r * 132 + k0 + tg + 4]);
                a[mt][3] = cvt_tf32(xs[(r + 8) * 132 + k0 + tg + 4]);
            }
#pragma unroll
            for (int nt = 0; nt < 8; nt++) {
                int jn = cb + nt * 8 + g;
                unsigned b0 = cvt_tf32(ws[jn * 132 + k0 + tg]);
                unsigned b1 = cvt_tf32(ws[jn * 132 + k0 + tg + 4]);
                mma_tf32(c[0][nt], a[0][0], a[0][1], a[0][2], a[0][3], b0, b1);
                mma_tf32(c[1][nt], a[1][0], a[1][1], a[1][2], a[1][3], b0, b1);
            }
        }

        const float scale = (w == 0) ? 0.25f : 1.0f;  // fold 1/sqrt(HD) into Q
        __nv_bfloat162* OUT = reinterpret_cast<__nv_bfloat162*>(Os[w]);
#pragma unroll
        for (int mt = 0; mt < 2; mt++) {
#pragma unroll
            for (int nt = 0; nt < 8; nt++) {
                int cp = (cb + nt * 8 + 2 * tg) >> 1;   // bf16x2 index
                int r1 = row0 + rb + mt * 16 + g;
                int r2 = r1 + 8;
                if (r1 < n)
                    OUT[r1 * 64 + cp] = __floats2bfloat162_rn(
                        c[mt][nt][0] * scale, c[mt][nt][1] * scale);
                if (r2 < n)
                    OUT[r2 * 64 + cp] = __floats2bfloat162_rn(
                        c[mt][nt][2] * scale, c[mt][nt][3] * scale);
            }
        }
    }
}

// ---------------- per-edge attention + scatter-add --------------------------
__global__ void __launch_bounds__(256)
edge_kernel(int E)
{
    const int gw   = (blockIdx.x * blockDim.x + threadIdx.x) >> 5;
    const int lane = threadIdx.x & 31;
    if (gw >= E) return;

    const int row = __ldg(&g_row[gw]);
    const int col = __ldg(&g_col[gw]);
    float ew = __ldg(&g_ew[gw]);

    const uint2* Q2 = reinterpret_cast<const uint2*>(g_Qh);
    const uint2* K2 = reinterpret_cast<const uint2*>(g_Kh);
    const uint2* V2 = reinterpret_cast<const uint2*>(g_Vh);

    uint2 qu = Q2[row * 32 + lane];
    uint2 ku = K2[col * 32 + lane];
    uint2 vu = V2[row * 32 + lane];

    float2 q01 = __bfloat1622float2(*reinterpret_cast<__nv_bfloat162*>(&qu.x));
    float2 q23 = __bfloat1622float2(*reinterpret_cast<__nv_bfloat162*>(&qu.y));
    float2 k01 = __bfloat1622float2(*reinterpret_cast<__nv_bfloat162*>(&ku.x));
    float2 k23 = __bfloat1622float2(*reinterpret_cast<__nv_bfloat162*>(&ku.y));
    float2 v01 = __bfloat1622float2(*reinterpret_cast<__nv_bfloat162*>(&vu.x));
    float2 v23 = __bfloat1622float2(*reinterpret_cast<__nv_bfloat162*>(&vu.y));

    float s = q01.x * k01.x + q01.y * k01.y + q23.x * k23.x + q23.y * k23.y;
    s += __shfl_xor_sync(0xffffffffu, s, 1);
    s += __shfl_xor_sync(0xffffffffu, s, 2);
    s = (s > 0.f) ? s : ALPHA * s;
    s *= ew;

    float m = s;
    m = fmaxf(m, __shfl_xor_sync(0xffffffffu, m, 4));
    m = fmaxf(m, __shfl_xor_sync(0xffffffffu, m, 8));
    m = fmaxf(m, __shfl_xor_sync(0xffffffffu, m, 16));
    float p = __expf(s - m);
    float den = p;
    den += __shfl_xor_sync(0xffffffffu, den, 4);
    den += __shfl_xor_sync(0xffffffffu, den, 8);
    den += __shfl_xor_sync(0xffffffffu, den, 16);
    p /= den;

    float* dst = g_AGG + col * DMODEL + lane * 4;
    asm volatile("red.global.add.v4.f32 [%0], {%1, %2, %3, %4};"
                 :: "l"(dst), "f"(p * v01.x), "f"(p * v01.y),
                    "f"(p * v23.x), "f"(p * v23.y)
                 : "memory");
}

// ---------------- output projection + residual + LayerNorm (tf32 MMA) -------
// Same warp layout as qkv. After MMA, result staged back into ws, then
// 8 warps do residual + LN with float4 smem reads.
#define OUT_SMEM (2 * 128 * 132 * 4)

__global__ void __launch_bounds__(256, 1)
out_ln_kernel(const float* __restrict__ x,
              const float* __restrict__ Wo,
              const float* __restrict__ bo,
              const float* __restrict__ gamma,
              const float* __restrict__ beta,
              float* __restrict__ out,
              int n)
{
    extern __shared__ float sm[];
    float* as = sm;              // [128][132]  AGG tile
    float* ws = sm + 128 * 132;  // [128][132]  Wo, then result staging

    const int row0 = blockIdx.x * 128;
    const int tid  = threadIdx.x;
    const int warp = tid >> 5;
    const int lane = tid & 31;
    const int g    = lane >> 2;
    const int tg   = lane & 3;
    const int wr   = warp & 3;
    const int wc   = warp >> 2;
    const int rb   = wr * 32;
    const int cb   = wc * 64;

    for (int t = tid; t < 128 * 32; t += 256) {
        int r  = t >> 5;
        int c4 = t & 31;
        float4 v = make_float4(0.f, 0.f, 0.f, 0.f);
        int gr = row0 + r;
        if (gr < n) v = reinterpret_cast<const float4*>(g_AGG)[gr * 32 + c4];
        float* d = as + r * 132 + c4 * 4;
        d[0] = v.x; d[1] = v.y; d[2] = v.z; d[3] = v.w;
    }
    for (int t = tid; t < 128 * 32; t += 256) {
        int r  = t >> 5;
        int c4 = t & 31;
        float4 v = reinterpret_cast<const float4*>(Wo)[r * 32 + c4];
        float* d = ws + r * 132 + c4 * 4;
        d[0] = v.x; d[1] = v.y; d[2] = v.z; d[3] = v.w;
    }
    __syncthreads();

    float c[2][8][4];
#pragma unroll
    for (int mt = 0; mt < 2; mt++)
#pragma unroll
        for (int nt = 0; nt < 8; nt++)
#pragma unroll
            for (int i = 0; i < 4; i++) c[mt][nt][i] = 0.f;

#pragma unroll 4
    for (int kt = 0; kt < 16; kt++) {
        const int k0 = kt * 8;
        unsigned a[2][4];
#pragma unroll
        for (int mt = 0; mt < 2; mt++) {
            int r = rb + mt * 16 + g;
            a[mt][0] = cvt_tf32(as[r * 132 + k0 + tg]);
            a[mt][1] = cvt_tf32(as[(r + 8) * 132 + k0 + tg]);
            a[mt][2] = cvt_tf32(as[r * 132 + k0 + tg + 4]);
            a[mt][3] = cvt_tf32(as[(r + 8) * 132 + k0 + tg + 4]);
        }
#pragma unroll
        for (int nt = 0; nt < 8; nt++) {
            int jn = cb + nt * 8 + g;
            unsigned b0 = cvt_tf32(ws[jn * 132 + k0 + tg]);
            unsigned b1 = cvt_tf32(ws[jn * 132 + k0 + tg + 4]);
            mma_tf32(c[0][nt], a[0][0], a[0][1], a[0][2], a[0][3], b0, b1);
            mma_tf32(c[1][nt], a[1][0], a[1][1], a[1][2], a[1][3], b0, b1);
        }
    }

    __syncthreads();  // everyone done reading ws; reuse it for staging
#pragma unroll
    for (int mt = 0; mt < 2; mt++) {
#pragma unroll
        for (int nt = 0; nt < 8; nt++) {
            int r1 = rb + mt * 16 + g;
            int cc = cb + nt * 8 + 2 * tg;
            ws[r1 * 132 + cc]       = c[mt][nt][0];
            ws[r1 * 132 + cc + 1]   = c[mt][nt][1];
            ws[(r1 + 8) * 132 + cc]     = c[mt][nt][2];
            ws[(r1 + 8) * 132 + cc + 1] = c[mt][nt][3];
        }
    }
    __syncthreads();

    float4 bo4 = reinterpret_cast<const float4*>(bo)[lane];
    float4 g4  = reinterpret_cast<const float4*>(gamma)[lane];
    float4 b4  = reinterpret_cast<const float4*>(beta)[lane];

    for (int r = warp; r < 128; r += 8) {
        int gr = row0 + r;
        if (gr >= n) continue;
        float4 a  = *reinterpret_cast<float4*>(ws + r * 132 + lane * 4);
        float4 xv = reinterpret_cast<const float4*>(x)[gr * 32 + lane];
        float o0 = a.x + bo4.x + xv.x;
        float o1 = a.y + bo4.y + xv.y;
        float o2 = a.z + bo4.z + xv.z;
        float o3 = a.w + bo4.w + xv.w;

        float s  = o0 + o1 + o2 + o3;
        float ss = o0 * o0 + o1 * o1 + o2 * o2 + o3 * o3;
#pragma unroll
        for (int off = 16; off >= 1; off >>= 1) {
            s  += __shfl_xor_sync(0xffffffffu, s,  off);
            ss += __shfl_xor_sync(0xffffffffu, ss, off);
        }
        float mu  = s * (1.f / 128.f);
        float var = ss * (1.f / 128.f) - mu * mu;
        float inv = rsqrtf(var + LN_EPS);

        float4 o;
        o.x = (o0 - mu) * inv * g4.x + b4.x;
        o.y = (o1 - mu) * inv * g4.y + b4.y;
        o.z = (o2 - mu) * inv * g4.z + b4.z;
        o.w = (o3 - mu) * inv * g4.w + b4.w;
        reinterpret_cast<float4*>(out)[gr * 32 + lane] = o;
    }
}

// ---------------- launcher ---------------------------------------------------
extern "C" void kernel_launch(void* const* d_in, const int* in_sizes, int n_in,
                              void* d_out, int out_size)
{
    const float* x     = (const float*)d_in[0];
    const void*  ei    = d_in[1];
    const float* eattr = (const float*)d_in[2];
    const float* Wq    = (const float*)d_in[3];
    const float* Wk    = (const float*)d_in[4];
    const float* Wv    = (const float*)d_in[5];
    const float* Wo    = (const float*)d_in[6];
    const float* bo    = (const float*)d_in[7];
    const float* gamma = (const float*)d_in[8];
    const float* beta  = (const float*)d_in[9];
    float* out = (float*)d_out;

    int n = in_sizes[0] / DMODEL;
    int E = in_sizes[1] / 2;
    if (n > NMAX) n = NMAX;

    cudaFuncSetAttribute(qkv_kernel,
                         cudaFuncAttributeMaxDynamicSharedMemorySize, QKV_SMEM);
    cudaFuncSetAttribute(out_ln_kernel,
                         cudaFuncAttributeMaxDynamicSharedMemorySize, OUT_SMEM);

    detect_kernel<<<1, 32>>>((const unsigned*)ei, E);
    prep_kernel<<<(E + 255) / 256, 256>>>(ei, eattr, E);
    zero_kernel<<<512, 256>>>(n * 32);

    int nrb = (n + 127) / 128;
    qkv_kernel<<<nrb, 256, QKV_SMEM>>>(x, Wq, Wk, Wv, n);

    long long ethreads = (long long)E * 32;
    int eblocks = (int)((ethreads + 255) / 256);
    edge_kernel<<<eblocks, 256>>>(E);

    out_ln_kernel<<<nrb, 256, OUT_SMEM>>>(x, Wo, bo, gamma, beta, out, n);
}

// round 6
// speedup vs baseline: 1.8202x; 1.2656x over previous
#include <cuda_runtime.h>
#include <cuda_bf16.h>
#include <math.h>

#define NMAX    50000
#define DMODEL  128
#define ALPHA   0.2f
#define LN_EPS  1e-5f

// ---------------- scratch (device globals; no allocations allowed) ----------
__device__ __align__(16) __nv_bfloat16 g_Qh[NMAX * DMODEL];
__device__ __align__(16) __nv_bfloat16 g_Kh[NMAX * DMODEL];
__device__ __align__(16) __nv_bfloat16 g_Vh[NMAX * DMODEL];
__device__ __align__(16) float g_AGG[NMAX * DMODEL];
__device__ __align__(16) float g_ew[800000 + 64];
__device__ __align__(16) int   g_row[800000 + 64];
__device__ __align__(16) int   g_col[800000 + 64];
__device__ int g_is64;

// ---------------- tf32 mma helpers ------------------------------------------
__device__ __forceinline__ unsigned cvt_tf32(float f)
{
    unsigned u;
    asm("cvt.rna.tf32.f32 %0, %1;" : "=r"(u) : "f"(f));
    return u;
}

__device__ __forceinline__ void mma_tf32(float c[4],
                                         unsigned a0, unsigned a1,
                                         unsigned a2, unsigned a3,
                                         unsigned b0, unsigned b1)
{
    asm("mma.sync.aligned.m16n8k8.row.col.f32.tf32.tf32.f32 "
        "{%0,%1,%2,%3}, {%4,%5,%6,%7}, {%8,%9}, {%0,%1,%2,%3};"
        : "+f"(c[0]), "+f"(c[1]), "+f"(c[2]), "+f"(c[3])
        : "r"(a0), "r"(a1), "r"(a2), "r"(a3), "r"(b0), "r"(b1));
}

// ---------------- detect edge_index dtype (int32 vs int64) ------------------
__global__ void detect_kernel(const unsigned* __restrict__ ei, int E)
{
    if (blockIdx.x == 0 && threadIdx.x == 0) {
        int is64 = 1;
        int m = (E >= 64) ? 64 : E;
        for (int i = 0; i < m; i++) {
            if (ei[2 * i + 1] != 0u) { is64 = 0; break; }
        }
        g_is64 = is64;
    }
}

// ---------------- prep: int32 indices + edge gate ----------------------------
__global__ void prep_kernel(const void* __restrict__ eiv,
                            const float* __restrict__ eattr,
                            int E)
{
    int e = blockIdx.x * blockDim.x + threadIdx.x;
    if (e >= E) return;

    int row, col;
    if (g_is64) {
        const long long* p = reinterpret_cast<const long long*>(eiv);
        row = (int)p[e];
        col = (int)p[(long long)E + e];
    } else {
        const int* p = reinterpret_cast<const int*>(eiv);
        row = p[e];
        col = p[E + e];
    }
    g_row[e] = row;
    g_col[e] = col;

    const float4* a4 = reinterpret_cast<const float4*>(eattr) + (size_t)e * 4;
    float s = 0.f;
#pragma unroll
    for (int i = 0; i < 4; i++) {
        float4 a = a4[i];
        s += a.x + a.y + a.z + a.w;
    }
    g_ew[e] = 1.f / (1.f + __expf(-s));
}

// ---------------- zero the aggregation buffer -------------------------------
__global__ void zero_kernel(int n4)
{
    float4 z = make_float4(0.f, 0.f, 0.f, 0.f);
    float4* p = reinterpret_cast<float4*>(g_AGG);
    for (int i = blockIdx.x * blockDim.x + threadIdx.x; i < n4;
         i += gridDim.x * blockDim.x)
        p[i] = z;
}

// ---------------- fused QKV projection GEMM (tf32 MMA, bf16 out) ------------
// Block = 128 rows; x tile converted to tf32 in smem ONCE; loops over the 3
// weights x 2 column-halves (ws tile = 64x132 -> total smem 101.4KB -> 2
// blocks/SM = 16 resident warps). Inner loop is pure LDS+MMA (no cvt).
// 8 warps as 4x2 over (128 rows x 64 cols): warp = 2 m-tiles x 4 n-tiles.
#define QKV_SMEM ((128 * 132 + 64 * 132) * 4)

__global__ void __launch_bounds__(256, 2)
qkv_kernel(const float* __restrict__ x,
           const float* __restrict__ Wq,
           const float* __restrict__ Wk,
           const float* __restrict__ Wv,
           int n)
{
    extern __shared__ unsigned smu[];
    unsigned* xs = smu;              // [128][132] tf32
    unsigned* ws = smu + 128 * 132;  // [64][132]  tf32

    const int row0 = blockIdx.x * 128;
    const int tid  = threadIdx.x;
    const int warp = tid >> 5;
    const int lane = tid & 31;
    const int g    = lane >> 2;   // 0..7
    const int tg   = lane & 3;    // 0..3
    const int rb   = (warp & 3) * 32;   // row base
    const int cb   = (warp >> 2) * 32;  // col base within 64-col half

    // load + convert x tile once
    for (int t = tid; t < 128 * 32; t += 256) {
        int r  = t >> 5;
        int c4 = t & 31;
        float4 v = make_float4(0.f, 0.f, 0.f, 0.f);
        int gr = row0 + r;
        if (gr < n) v = reinterpret_cast<const float4*>(x)[gr * 32 + c4];
        unsigned* d = xs + r * 132 + c4 * 4;
        d[0] = cvt_tf32(v.x); d[1] = cvt_tf32(v.y);
        d[2] = cvt_tf32(v.z); d[3] = cvt_tf32(v.w);
    }

    const float* Ws[3]   = {Wq, Wk, Wv};
    __nv_bfloat16* Os[3] = {g_Qh, g_Kh, g_Vh};

    for (int w = 0; w < 3; w++) {
        const float* W = Ws[w];
        const float scale = (w == 0) ? 0.25f : 1.0f;  // fold 1/sqrt(HD) into Q
        __nv_bfloat162* OUT = reinterpret_cast<__nv_bfloat162*>(Os[w]);

        for (int h = 0; h < 2; h++) {
            __syncthreads();  // xs ready / previous users of ws done
            for (int t = tid; t < 64 * 32; t += 256) {
                int r  = t >> 5;
                int c4 = t & 31;
                float4 v = reinterpret_cast<const float4*>(W)[(h * 64 + r) * 32 + c4];
                unsigned* d = ws + r * 132 + c4 * 4;
                d[0] = cvt_tf32(v.x); d[1] = cvt_tf32(v.y);
                d[2] = cvt_tf32(v.z); d[3] = cvt_tf32(v.w);
            }
            __syncthreads();

            float c[2][4][4];
#pragma unroll
            for (int mt = 0; mt < 2; mt++)
#pragma unroll
                for (int nt = 0; nt < 4; nt++)
#pragma unroll
                    for (int i = 0; i < 4; i++) c[mt][nt][i] = 0.f;

#pragma unroll 4
            for (int kt = 0; kt < 16; kt++) {
                const int k0 = kt * 8;
                unsigned a[2][4];
#pragma unroll
                for (int mt = 0; mt < 2; mt++) {
                    int r = rb + mt * 16 + g;
                    a[mt][0] = xs[r * 132 + k0 + tg];
                    a[mt][1] = xs[(r + 8) * 132 + k0 + tg];
                    a[mt][2] = xs[r * 132 + k0 + tg + 4];
                    a[mt][3] = xs[(r + 8) * 132 + k0 + tg + 4];
                }
#pragma unroll
                for (int nt = 0; nt < 4; nt++) {
                    int jn = cb + nt * 8 + g;
                    unsigned b0 = ws[jn * 132 + k0 + tg];
                    unsigned b1 = ws[jn * 132 + k0 + tg + 4];
                    mma_tf32(c[0][nt], a[0][0], a[0][1], a[0][2], a[0][3], b0, b1);
                    mma_tf32(c[1][nt], a[1][0], a[1][1], a[1][2], a[1][3], b0, b1);
                }
            }

#pragma unroll
            for (int mt = 0; mt < 2; mt++) {
#pragma unroll
                for (int nt = 0; nt < 4; nt++) {
                    int cp = (h * 64 + cb + nt * 8 + 2 * tg) >> 1;  // bf16x2 idx
                    int r1 = row0 + rb + mt * 16 + g;
                    int r2 = r1 + 8;
                    if (r1 < n)
                        OUT[r1 * 64 + cp] = __floats2bfloat162_rn(
                            c[mt][nt][0] * scale, c[mt][nt][1] * scale);
                    if (r2 < n)
                        OUT[r2 * 64 + cp] = __floats2bfloat162_rn(
                            c[mt][nt][2] * scale, c[mt][nt][3] * scale);
                }
            }
        }
    }
}

// ---------------- per-edge attention + scatter-add --------------------------
__global__ void __launch_bounds__(256)
edge_kernel(int E)
{
    const int gw   = (blockIdx.x * blockDim.x + threadIdx.x) >> 5;
    const int lane = threadIdx.x & 31;
    if (gw >= E) return;

    const int row = __ldg(&g_row[gw]);
    const int col = __ldg(&g_col[gw]);
    float ew = __ldg(&g_ew[gw]);

    const uint2* Q2 = reinterpret_cast<const uint2*>(g_Qh);
    const uint2* K2 = reinterpret_cast<const uint2*>(g_Kh);
    const uint2* V2 = reinterpret_cast<const uint2*>(g_Vh);

    uint2 qu = Q2[row * 32 + lane];
    uint2 ku = K2[col * 32 + lane];
    uint2 vu = V2[row * 32 + lane];

    float2 q01 = __bfloat1622float2(*reinterpret_cast<__nv_bfloat162*>(&qu.x));
    float2 q23 = __bfloat1622float2(*reinterpret_cast<__nv_bfloat162*>(&qu.y));
    float2 k01 = __bfloat1622float2(*reinterpret_cast<__nv_bfloat162*>(&ku.x));
    float2 k23 = __bfloat1622float2(*reinterpret_cast<__nv_bfloat162*>(&ku.y));
    float2 v01 = __bfloat1622float2(*reinterpret_cast<__nv_bfloat162*>(&vu.x));
    float2 v23 = __bfloat1622float2(*reinterpret_cast<__nv_bfloat162*>(&vu.y));

    float s = q01.x * k01.x + q01.y * k01.y + q23.x * k23.x + q23.y * k23.y;
    s += __shfl_xor_sync(0xffffffffu, s, 1);
    s += __shfl_xor_sync(0xffffffffu, s, 2);
    s = (s > 0.f) ? s : ALPHA * s;
    s *= ew;

    float m = s;
    m = fmaxf(m, __shfl_xor_sync(0xffffffffu, m, 4));
    m = fmaxf(m, __shfl_xor_sync(0xffffffffu, m, 8));
    m = fmaxf(m, __shfl_xor_sync(0xffffffffu, m, 16));
    float p = __expf(s - m);
    float den = p;
    den += __shfl_xor_sync(0xffffffffu, den, 4);
    den += __shfl_xor_sync(0xffffffffu, den, 8);
    den += __shfl_xor_sync(0xffffffffu, den, 16);
    p /= den;

    float* dst = g_AGG + col * DMODEL + lane * 4;
    asm volatile("red.global.add.v4.f32 [%0], {%1, %2, %3, %4};"
                 :: "l"(dst), "f"(p * v01.x), "f"(p * v01.y),
                    "f"(p * v23.x), "f"(p * v23.y)
                 : "memory");
}

// ---------------- output projection + residual + LayerNorm (tf32 MMA) -------
// Same structure as qkv: as tile tf32 (converted once), ws = 64x132 halves.
// Both halves' accumulators kept live; result staged into `as` (free after
// the last MMA), then 8 warps do residual + LN.
#define OUT_SMEM ((128 * 132 + 64 * 132) * 4)

__global__ void __launch_bounds__(256, 2)
out_ln_kernel(const float* __restrict__ x,
              const float* __restrict__ Wo,
              const float* __restrict__ bo,
              const float* __restrict__ gamma,
              const float* __restrict__ beta,
              float* __restrict__ out,
              int n)
{
    extern __shared__ unsigned smu[];
    unsigned* as = smu;              // [128][132] tf32 AGG, later fp32 result
    unsigned* ws = smu + 128 * 132;  // [64][132]  tf32 Wo half

    const int row0 = blockIdx.x * 128;
    const int tid  = threadIdx.x;
    const int warp = tid >> 5;
    const int lane = tid & 31;
    const int g    = lane >> 2;
    const int tg   = lane & 3;
    const int rb   = (warp & 3) * 32;
    const int cb   = (warp >> 2) * 32;

    for (int t = tid; t < 128 * 32; t += 256) {
        int r  = t >> 5;
        int c4 = t & 31;
        float4 v = make_float4(0.f, 0.f, 0.f, 0.f);
        int gr = row0 + r;
        if (gr < n) v = reinterpret_cast<const float4*>(g_AGG)[gr * 32 + c4];
        unsigned* d = as + r * 132 + c4 * 4;
        d[0] = cvt_tf32(v.x); d[1] = cvt_tf32(v.y);
        d[2] = cvt_tf32(v.z); d[3] = cvt_tf32(v.w);
    }

    float c[2][2][4][4];   // [half][mt][nt][i]
#pragma unroll
    for (int h = 0; h < 2; h++)
#pragma unroll
        for (int mt = 0; mt < 2; mt++)
#pragma unroll
            for (int nt = 0; nt < 4; nt++)
#pragma unroll
                for (int i = 0; i < 4; i++) c[h][mt][nt][i] = 0.f;

    for (int h = 0; h < 2; h++) {
        __syncthreads();
        for (int t = tid; t < 64 * 32; t += 256) {
            int r  = t >> 5;
            int c4 = t & 31;
            float4 v = reinterpret_cast<const float4*>(Wo)[(h * 64 + r) * 32 + c4];
            unsigned* d = ws + r * 132 + c4 * 4;
            d[0] = cvt_tf32(v.x); d[1] = cvt_tf32(v.y);
            d[2] = cvt_tf32(v.z); d[3] = cvt_tf32(v.w);
        }
        __syncthreads();

#pragma unroll 4
        for (int kt = 0; kt < 16; kt++) {
            const int k0 = kt * 8;
            unsigned a[2][4];
#pragma unroll
            for (int mt = 0; mt < 2; mt++) {
                int r = rb + mt * 16 + g;
                a[mt][0] = as[r * 132 + k0 + tg];
                a[mt][1] = as[(r + 8) * 132 + k0 + tg];
                a[mt][2] = as[r * 132 + k0 + tg + 4];
                a[mt][3] = as[(r + 8) * 132 + k0 + tg + 4];
            }
#pragma unroll
            for (int nt = 0; nt < 4; nt++) {
                int jn = cb + nt * 8 + g;
                unsigned b0 = ws[jn * 132 + k0 + tg];
                unsigned b1 = ws[jn * 132 + k0 + tg + 4];
                mma_tf32(c[h][0][nt], a[0][0], a[0][1], a[0][2], a[0][3], b0, b1);
                mma_tf32(c[h][1][nt], a[1][0], a[1][1], a[1][2], a[1][3], b0, b1);
            }
        }
    }

    __syncthreads();  // all MMAs done reading `as`; reuse it as fp32 staging
    float* res = reinterpret_cast<float*>(as);
#pragma unroll
    for (int h = 0; h < 2; h++)
#pragma unroll
        for (int mt = 0; mt < 2; mt++)
#pragma unroll
            for (int nt = 0; nt < 4; nt++) {
                int r1 = rb + mt * 16 + g;
                int cc = h * 64 + cb + nt * 8 + 2 * tg;
                res[r1 * 132 + cc]           = c[h][mt][nt][0];
                res[r1 * 132 + cc + 1]       = c[h][mt][nt][1];
                res[(r1 + 8) * 132 + cc]     = c[h][mt][nt][2];
                res[(r1 + 8) * 132 + cc + 1] = c[h][mt][nt][3];
            }
    __syncthreads();

    float4 bo4 = reinterpret_cast<const float4*>(bo)[lane];
    float4 g4  = reinterpret_cast<const float4*>(gamma)[lane];
    float4 b4  = reinterpret_cast<const float4*>(beta)[lane];

    for (int r = warp; r < 128; r += 8) {
        int gr = row0 + r;
        if (gr >= n) continue;
        float4 a  = *reinterpret_cast<float4*>(res + r * 132 + lane * 4);
        float4 xv = reinterpret_cast<const float4*>(x)[gr * 32 + lane];
        float o0 = a.x + bo4.x + xv.x;
        float o1 = a.y + bo4.y + xv.y;
        float o2 = a.z + bo4.z + xv.z;
        float o3 = a.w + bo4.w + xv.w;

        float s  = o0 + o1 + o2 + o3;
        float ss = o0 * o0 + o1 * o1 + o2 * o2 + o3 * o3;
#pragma unroll
        for (int off = 16; off >= 1; off >>= 1) {
            s  += __shfl_xor_sync(0xffffffffu, s,  off);
            ss += __shfl_xor_sync(0xffffffffu, ss, off);
        }
        float mu  = s * (1.f / 128.f);
        float var = ss * (1.f / 128.f) - mu * mu;
        float inv = rsqrtf(var + LN_EPS);

        float4 o;
        o.x = (o0 - mu) * inv * g4.x + b4.x;
        o.y = (o1 - mu) * inv * g4.y + b4.y;
        o.z = (o2 - mu) * inv * g4.z + b4.z;
        o.w = (o3 - mu) * inv * g4.w + b4.w;
        reinterpret_cast<float4*>(out)[gr * 32 + lane] = o;
    }
}

// ---------------- launcher ---------------------------------------------------
extern "C" void kernel_launch(void* const* d_in, const int* in_sizes, int n_in,
                              void* d_out, int out_size)
{
    const float* x     = (const float*)d_in[0];
    const void*  ei    = d_in[1];
    const float* eattr = (const float*)d_in[2];
    const float* Wq    = (const float*)d_in[3];
    const float* Wk    = (const float*)d_in[4];
    const float* Wv    = (const float*)d_in[5];
    const float* Wo    = (const float*)d_in[6];
    const float* bo    = (const float*)d_in[7];
    const float* gamma = (const float*)d_in[8];
    const float* beta  = (const float*)d_in[9];
    float* out = (float*)d_out;

    int n = in_sizes[0] / DMODEL;
    int E = in_sizes[1] / 2;
    if (n > NMAX) n = NMAX;

    cudaFuncSetAttribute(qkv_kernel,
                         cudaFuncAttributeMaxDynamicSharedMemorySize, QKV_SMEM);
    cudaFuncSetAttribute(out_ln_kernel,
                         cudaFuncAttributeMaxDynamicSharedMemorySize, OUT_SMEM);

    detect_kernel<<<1, 32>>>((const unsigned*)ei, E);
    prep_kernel<<<(E + 255) / 256, 256>>>(ei, eattr, E);
    zero_kernel<<<512, 256>>>(n * 32);

    int nrb = (n + 127) / 128;
    qkv_kernel<<<nrb, 256, QKV_SMEM>>>(x, Wq, Wk, Wv, n);

    long long ethreads = (long long)E * 32;
    int eblocks = (int)((ethreads + 255) / 256);
    edge_kernel<<<eblocks, 256>>>(E);

    out_ln_kernel<<<nrb, 256, OUT_SMEM>>>(x, Wo, bo, gamma, beta, out, n);
}

// round 7
// speedup vs baseline: 1.8341x; 1.0076x over previous
#include <cuda_runtime.h>
#include <cuda_bf16.h>
#include <math.h>

#define NMAX    50000
#define DMODEL  128
#define ALPHA   0.2f
#define LN_EPS  1e-5f

// ---------------- scratch (device globals; no allocations allowed) ----------
__device__ __align__(16) __nv_bfloat16 g_Qh[NMAX * DMODEL];
__device__ __align__(16) __nv_bfloat16 g_Kh[NMAX * DMODEL];
__device__ __align__(16) __nv_bfloat16 g_Vh[NMAX * DMODEL];
__device__ __align__(16) float g_AGG[NMAX * DMODEL];
__device__ __align__(16) float g_ew[800000 + 64];
__device__ __align__(16) int   g_row[800000 + 64];
__device__ __align__(16) int   g_col[800000 + 64];
__device__ __align__(16) unsigned g_W32[3 * DMODEL * DMODEL];   // Wq,Wk,Wv tf32
__device__ __align__(16) unsigned g_Wo32[DMODEL * DMODEL];      // Wo tf32
__device__ int g_is64;

// ---------------- tf32 mma helpers ------------------------------------------
__device__ __forceinline__ unsigned cvt_tf32(float f)
{
    unsigned u;
    asm("cvt.rna.tf32.f32 %0, %1;" : "=r"(u) : "f"(f));
    return u;
}

__device__ __forceinline__ void mma_tf32(float c[4],
                                         unsigned a0, unsigned a1,
                                         unsigned a2, unsigned a3,
                                         unsigned b0, unsigned b1)
{
    asm("mma.sync.aligned.m16n8k8.row.col.f32.tf32.tf32.f32 "
        "{%0,%1,%2,%3}, {%4,%5,%6,%7}, {%8,%9}, {%0,%1,%2,%3};"
        : "+f"(c[0]), "+f"(c[1]), "+f"(c[2]), "+f"(c[3])
        : "r"(a0), "r"(a1), "r"(a2), "r"(a3), "r"(b0), "r"(b1));
}

__device__ __forceinline__ void cp_async16(unsigned smem_dst, const void* gsrc)
{
    asm volatile("cp.async.cg.shared.global [%0], [%1], 16;"
                 :: "r"(smem_dst), "l"(gsrc));
}
__device__ __forceinline__ void cp_async_wait_all()
{
    asm volatile("cp.async.commit_group;");
    asm volatile("cp.async.wait_group 0;");
}

// ---------------- detect edge_index dtype (int32 vs int64) ------------------
__global__ void detect_kernel(const unsigned* __restrict__ ei, int E)
{
    if (blockIdx.x == 0 && threadIdx.x == 0) {
        int is64 = 1;
        int m = (E >= 64) ? 64 : E;
        for (int i = 0; i < m; i++) {
            if (ei[2 * i + 1] != 0u) { is64 = 0; break; }
        }
        g_is64 = is64;
    }
}

// ---------------- weight pre-conversion to tf32 ------------------------------
__global__ void wprep_kernel(const float* __restrict__ Wq,
                             const float* __restrict__ Wk,
                             const float* __restrict__ Wv,
                             const float* __restrict__ Wo)
{
    int i = blockIdx.x * blockDim.x + threadIdx.x;
    if (i < DMODEL * DMODEL) {
        g_W32[i]                       = cvt_tf32(Wq[i]);
        g_W32[DMODEL * DMODEL + i]     = cvt_tf32(Wk[i]);
        g_W32[2 * DMODEL * DMODEL + i] = cvt_tf32(Wv[i]);
        g_Wo32[i]                      = cvt_tf32(Wo[i]);
    }
}

// ---------------- prep: int32 indices + edge gate + AGG zero -----------------
__global__ void prep_kernel(const void* __restrict__ eiv,
                            const float* __restrict__ eattr,
                            int E, int n4)
{
    const int e = blockIdx.x * blockDim.x + threadIdx.x;
    if (e < E) {
        int row, col;
        if (g_is64) {
            const long long* p = reinterpret_cast<const long long*>(eiv);
            row = (int)p[e];
            col = (int)p[(long long)E + e];
        } else {
            const int* p = reinterpret_cast<const int*>(eiv);
            row = p[e];
            col = p[E + e];
        }
        g_row[e] = row;
        g_col[e] = col;

        const float4* a4 = reinterpret_cast<const float4*>(eattr) + (size_t)e * 4;
        float s = 0.f;
#pragma unroll
        for (int i = 0; i < 4; i++) {
            float4 a = a4[i];
            s += a.x + a.y + a.z + a.w;
        }
        g_ew[e] = 1.f / (1.f + __expf(-s));
    }
    // zero AGG (strided over the whole grid)
    const int total = gridDim.x * blockDim.x;
    float4 z = make_float4(0.f, 0.f, 0.f, 0.f);
    float4* p4 = reinterpret_cast<float4*>(g_AGG);
    for (int i = e; i < n4; i += total) p4[i] = z;
}

// ---------------- fused QKV projection GEMM (tf32 MMA, bf16 out) ------------
// grid (nrb, 2): block = 128 rows x one 64-col half of all 3 weights.
// xs converted to tf32 once; ws tiles copied (pre-converted) via cp.async.
// 8 warps as 4x2 over (128 rows x 64 cols).
#define QKV_SMEM ((128 * 132 + 64 * 132) * 4)

__global__ void __launch_bounds__(256, 2)
qkv_kernel(const float* __restrict__ x, int n)
{
    extern __shared__ unsigned smu[];
    unsigned* xs = smu;              // [128][132] tf32
    unsigned* ws = smu + 128 * 132;  // [64][132]  tf32

    const int row0 = blockIdx.x * 128;
    const int h    = blockIdx.y;          // column half: 0 or 1
    const int tid  = threadIdx.x;
    const int warp = tid >> 5;
    const int lane = tid & 31;
    const int g    = lane >> 2;
    const int tg   = lane & 3;
    const int rb   = (warp & 3) * 32;
    const int cb   = (warp >> 2) * 32;

    const unsigned ws_base =
        (unsigned)__cvta_generic_to_shared(ws);

    // load + convert x tile once
    for (int t = tid; t < 128 * 32; t += 256) {
        int r  = t >> 5;
        int c4 = t & 31;
        float4 v = make_float4(0.f, 0.f, 0.f, 0.f);
        int gr = row0 + r;
        if (gr < n) v = reinterpret_cast<const float4*>(x)[gr * 32 + c4];
        unsigned* d = xs + r * 132 + c4 * 4;
        d[0] = cvt_tf32(v.x); d[1] = cvt_tf32(v.y);
        d[2] = cvt_tf32(v.z); d[3] = cvt_tf32(v.w);
    }

    __nv_bfloat16* Os[3] = {g_Qh, g_Kh, g_Vh};

    for (int w = 0; w < 3; w++) {
        __syncthreads();  // xs ready (w=0) / prior MMA done with ws
        // copy pre-converted weight half rows [h*64, h*64+64)
        const unsigned* Wsrc = g_W32 + (w * DMODEL + h * 64) * DMODEL;
        for (int t = tid; t < 64 * 32; t += 256) {
            int r  = t >> 5;
            int c4 = t & 31;
            cp_async16(ws_base + (r * 132 + c4 * 4) * 4,
                       Wsrc + r * DMODEL + c4 * 4);
        }
        cp_async_wait_all();
        __syncthreads();

        float c[2][4][4];
#pragma unroll
        for (int mt = 0; mt < 2; mt++)
#pragma unroll
            for (int nt = 0; nt < 4; nt++)
#pragma unroll
                for (int i = 0; i < 4; i++) c[mt][nt][i] = 0.f;

#pragma unroll 4
        for (int kt = 0; kt < 16; kt++) {
            const int k0 = kt * 8;
            unsigned a[2][4];
#pragma unroll
            for (int mt = 0; mt < 2; mt++) {
                int r = rb + mt * 16 + g;
                a[mt][0] = xs[r * 132 + k0 + tg];
                a[mt][1] = xs[(r + 8) * 132 + k0 + tg];
                a[mt][2] = xs[r * 132 + k0 + tg + 4];
                a[mt][3] = xs[(r + 8) * 132 + k0 + tg + 4];
            }
#pragma unroll
            for (int nt = 0; nt < 4; nt++) {
                int jn = cb + nt * 8 + g;
                unsigned b0 = ws[jn * 132 + k0 + tg];
                unsigned b1 = ws[jn * 132 + k0 + tg + 4];
                mma_tf32(c[0][nt], a[0][0], a[0][1], a[0][2], a[0][3], b0, b1);
                mma_tf32(c[1][nt], a[1][0], a[1][1], a[1][2], a[1][3], b0, b1);
            }
        }

        const float scale = (w == 0) ? 0.25f : 1.0f;  // fold 1/sqrt(HD) into Q
        __nv_bfloat162* OUT = reinterpret_cast<__nv_bfloat162*>(Os[w]);
#pragma unroll
        for (int mt = 0; mt < 2; mt++) {
#pragma unroll
            for (int nt = 0; nt < 4; nt++) {
                int cp = (h * 64 + cb + nt * 8 + 2 * tg) >> 1;  // bf16x2 idx
                int r1 = row0 + rb + mt * 16 + g;
                int r2 = r1 + 8;
                if (r1 < n)
                    OUT[r1 * 64 + cp] = __floats2bfloat162_rn(
                        c[mt][nt][0] * scale, c[mt][nt][1] * scale);
                if (r2 < n)
                    OUT[r2 * 64 + cp] = __floats2bfloat162_rn(
                        c[mt][nt][2] * scale, c[mt][nt][3] * scale);
            }
        }
    }
}

// ---------------- per-edge attention + scatter-add --------------------------
__global__ void __launch_bounds__(256)
edge_kernel(int E)
{
    const int gw   = (blockIdx.x * blockDim.x + threadIdx.x) >> 5;
    const int lane = threadIdx.x & 31;
    if (gw >= E) return;

    const int row = __ldg(&g_row[gw]);
    const int col = __ldg(&g_col[gw]);
    float ew = __ldg(&g_ew[gw]);

    const uint2* Q2 = reinterpret_cast<const uint2*>(g_Qh);
    const uint2* K2 = reinterpret_cast<const uint2*>(g_Kh);
    const uint2* V2 = reinterpret_cast<const uint2*>(g_Vh);

    uint2 qu = Q2[row * 32 + lane];
    uint2 ku = K2[col * 32 + lane];
    uint2 vu = V2[row * 32 + lane];

    float2 q01 = __bfloat1622float2(*reinterpret_cast<__nv_bfloat162*>(&qu.x));
    float2 q23 = __bfloat1622float2(*reinterpret_cast<__nv_bfloat162*>(&qu.y));
    float2 k01 = __bfloat1622float2(*reinterpret_cast<__nv_bfloat162*>(&ku.x));
    float2 k23 = __bfloat1622float2(*reinterpret_cast<__nv_bfloat162*>(&ku.y));
    float2 v01 = __bfloat1622float2(*reinterpret_cast<__nv_bfloat162*>(&vu.x));
    float2 v23 = __bfloat1622float2(*reinterpret_cast<__nv_bfloat162*>(&vu.y));

    float s = q01.x * k01.x + q01.y * k01.y + q23.x * k23.x + q23.y * k23.y;
    s += __shfl_xor_sync(0xffffffffu, s, 1);
    s += __shfl_xor_sync(0xffffffffu, s, 2);
    s = (s > 0.f) ? s : ALPHA * s;
    s *= ew;

    float m = s;
    m = fmaxf(m, __shfl_xor_sync(0xffffffffu, m, 4));
    m = fmaxf(m, __shfl_xor_sync(0xffffffffu, m, 8));
    m = fmaxf(m, __shfl_xor_sync(0xffffffffu, m, 16));
    float p = __expf(s - m);
    float den = p;
    den += __shfl_xor_sync(0xffffffffu, den, 4);
    den += __shfl_xor_sync(0xffffffffu, den, 8);
    den += __shfl_xor_sync(0xffffffffu, den, 16);
    p /= den;

    float* dst = g_AGG + col * DMODEL + lane * 4;
    asm volatile("red.global.add.v4.f32 [%0], {%1, %2, %3, %4};"
                 :: "l"(dst), "f"(p * v01.x), "f"(p * v01.y),
                    "f"(p * v23.x), "f"(p * v23.y)
                 : "memory");
}

// ---------------- output projection + residual + LayerNorm (tf32 MMA) -------
#define OUT_SMEM ((128 * 132 + 64 * 132) * 4)

__global__ void __launch_bounds__(256, 2)
out_ln_kernel(const float* __restrict__ x,
              const float* __restrict__ bo,
              const float* __restrict__ gamma,
              const float* __restrict__ beta,
              float* __restrict__ out,
              int n)
{
    extern __shared__ unsigned smu[];
    unsigned* as = smu;              // [128][132] tf32 AGG, later fp32 result
    unsigned* ws = smu + 128 * 132;  // [64][132]  tf32 Wo half

    const int row0 = blockIdx.x * 128;
    const int tid  = threadIdx.x;
    const int warp = tid >> 5;
    const int lane = tid & 31;
    const int g    = lane >> 2;
    const int tg   = lane & 3;
    const int rb   = (warp & 3) * 32;
    const int cb   = (warp >> 2) * 32;

    const unsigned ws_base =
        (unsigned)__cvta_generic_to_shared(ws);

    for (int t = tid; t < 128 * 32; t += 256) {
        int r  = t >> 5;
        int c4 = t & 31;
        float4 v = make_float4(0.f, 0.f, 0.f, 0.f);
        int gr = row0 + r;
        if (gr < n) v = reinterpret_cast<const float4*>(g_AGG)[gr * 32 + c4];
        unsigned* d = as + r * 132 + c4 * 4;
        d[0] = cvt_tf32(v.x); d[1] = cvt_tf32(v.y);
        d[2] = cvt_tf32(v.z); d[3] = cvt_tf32(v.w);
    }

    float c[2][2][4][4];   // [half][mt][nt][i]
#pragma unroll
    for (int h = 0; h < 2; h++)
#pragma unroll
        for (int mt = 0; mt < 2; mt++)
#pragma unroll
            for (int nt = 0; nt < 4; nt++)
#pragma unroll
                for (int i = 0; i < 4; i++) c[h][mt][nt][i] = 0.f;

    for (int h = 0; h < 2; h++) {
        __syncthreads();
        const unsigned* Wsrc = g_Wo32 + (h * 64) * DMODEL;
        for (int t = tid; t < 64 * 32; t += 256) {
            int r  = t >> 5;
            int c4 = t & 31;
            cp_async16(ws_base + (r * 132 + c4 * 4) * 4,
                       Wsrc + r * DMODEL + c4 * 4);
        }
        cp_async_wait_all();
        __syncthreads();

#pragma unroll 4
        for (int kt = 0; kt < 16; kt++) {
            const int k0 = kt * 8;
            unsigned a[2][4];
#pragma unroll
            for (int mt = 0; mt < 2; mt++) {
                int r = rb + mt * 16 + g;
                a[mt][0] = as[r * 132 + k0 + tg];
                a[mt][1] = as[(r + 8) * 132 + k0 + tg];
                a[mt][2] = as[r * 132 + k0 + tg + 4];
                a[mt][3] = as[(r + 8) * 132 + k0 + tg + 4];
            }
#pragma unroll
            for (int nt = 0; nt < 4; nt++) {
                int jn = cb + nt * 8 + g;
                unsigned b0 = ws[jn * 132 + k0 + tg];
                unsigned b1 = ws[jn * 132 + k0 + tg + 4];
                mma_tf32(c[h][0][nt], a[0][0], a[0][1], a[0][2], a[0][3], b0, b1);
                mma_tf32(c[h][1][nt], a[1][0], a[1][1], a[1][2], a[1][3], b0, b1);
            }
        }
    }

    __syncthreads();  // all MMAs done reading `as`; reuse as fp32 staging
    float* res = reinterpret_cast<float*>(as);
#pragma unroll
    for (int h = 0; h < 2; h++)
#pragma unroll
        for (int mt = 0; mt < 2; mt++)
#pragma unroll
            for (int nt = 0; nt < 4; nt++) {
                int r1 = rb + mt * 16 + g;
                int cc = h * 64 + cb + nt * 8 + 2 * tg;
                res[r1 * 132 + cc]           = c[h][mt][nt][0];
                res[r1 * 132 + cc + 1]       = c[h][mt][nt][1];
                res[(r1 + 8) * 132 + cc]     = c[h][mt][nt][2];
                res[(r1 + 8) * 132 + cc + 1] = c[h][mt][nt][3];
            }
    __syncthreads();

    float4 bo4 = reinterpret_cast<const float4*>(bo)[lane];
    float4 g4  = reinterpret_cast<const float4*>(gamma)[lane];
    float4 b4  = reinterpret_cast<const float4*>(beta)[lane];

    for (int r = warp; r < 128; r += 8) {
        int gr = row0 + r;
        if (gr >= n) continue;
        float4 a  = *reinterpret_cast<float4*>(res + r * 132 + lane * 4);
        float4 xv = reinterpret_cast<const float4*>(x)[gr * 32 + lane];
        float o0 = a.x + bo4.x + xv.x;
        float o1 = a.y + bo4.y + xv.y;
        float o2 = a.z + bo4.z + xv.z;
        float o3 = a.w + bo4.w + xv.w;

        float s  = o0 + o1 + o2 + o3;
        float ss = o0 * o0 + o1 * o1 + o2 * o2 + o3 * o3;
#pragma unroll
        for (int off = 16; off >= 1; off >>= 1) {
            s  += __shfl_xor_sync(0xffffffffu, s,  off);
            ss += __shfl_xor_sync(0xffffffffu, ss, off);
        }
        float mu  = s * (1.f / 128.f);
        float var = ss * (1.f / 128.f) - mu * mu;
        float inv = rsqrtf(var + LN_EPS);

        float4 o;
        o.x = (o0 - mu) * inv * g4.x + b4.x;
        o.y = (o1 - mu) * inv * g4.y + b4.y;
        o.z = (o2 - mu) * inv * g4.z + b4.z;
        o.w = (o3 - mu) * inv * g4.w + b4.w;
        reinterpret_cast<float4*>(out)[gr * 32 + lane] = o;
    }
}

// ---------------- launcher ---------------------------------------------------
extern "C" void kernel_launch(void* const* d_in, const int* in_sizes, int n_in,
                              void* d_out, int out_size)
{
    const float* x     = (const float*)d_in[0];
    const void*  ei    = d_in[1];
    const float* eattr = (const float*)d_in[2];
    const float* Wq    = (const float*)d_in[3];
    const float* Wk    = (const float*)d_in[4];
    const float* Wv    = (const float*)d_in[5];
    const float* Wo    = (const float*)d_in[6];
    const float* bo    = (const float*)d_in[7];
    const float* gamma = (const float*)d_in[8];
    const float* beta  = (const float*)d_in[9];
    float* out = (float*)d_out;

    int n = in_sizes[0] / DMODEL;
    int E = in_sizes[1] / 2;
    if (n > NMAX) n = NMAX;

    cudaFuncSetAttribute(qkv_kernel,
                         cudaFuncAttributeMaxDynamicSharedMemorySize, QKV_SMEM);
    cudaFuncSetAttribute(out_ln_kernel,
                         cudaFuncAttributeMaxDynamicSharedMemorySize, OUT_SMEM);

    detect_kernel<<<1, 32>>>((const unsigned*)ei, E);
    wprep_kernel<<<(DMODEL * DMODEL + 255) / 256, 256>>>(Wq, Wk, Wv, Wo);
    prep_kernel<<<(E + 255) / 256, 256>>>(ei, eattr, E, n * 32);

    int nrb = (n + 127) / 128;
    qkv_kernel<<<dim3(nrb, 2), 256, QKV_SMEM>>>(x, n);

    long long ethreads = (long long)E * 32;
    int eblocks = (int)((ethreads + 255) / 256);
    edge_kernel<<<eblocks, 256>>>(E);

    out_ln_kernel<<<nrb, 256, OUT_SMEM>>>(x, bo, gamma, beta, out, n);
}

// round 9
// speedup vs baseline: 1.9975x; 1.0891x over previous
#include <cuda_runtime.h>
#include <cuda_bf16.h>
#include <math.h>

#define NMAX    50000
#define DMODEL  128
#define ALPHA   0.2f
#define LN_EPS  1e-5f

// K=128 bf16 => 64 u32 per row; stride 68 (4 pad) => bank = (4g+tg) mod 32, CF.
#define TSTRIDE 68

// ---------------- scratch (device globals; no allocations allowed) ----------
__device__ __align__(16) __nv_bfloat16 g_Qh[NMAX * DMODEL];
__device__ __align__(16) __nv_bfloat16 g_Kh[NMAX * DMODEL];
__device__ __align__(16) __nv_bfloat16 g_Vh[NMAX * DMODEL];
__device__ __align__(16) float g_AGG[NMAX * DMODEL];
__device__ __align__(16) float g_ew[800000 + 64];
__device__ __align__(16) int   g_row[800000 + 64];
__device__ __align__(16) int   g_col[800000 + 64];
__device__ __align__(16) unsigned g_Wb32[3 * DMODEL * 64];   // Wq,Wk,Wv bf16x2
__device__ __align__(16) unsigned g_Wob32[DMODEL * 64];      // Wo bf16x2
__device__ int g_is64;

// ---------------- bf16 mma helpers ------------------------------------------
__device__ __forceinline__ void mma_bf16(float c[4],
                                         unsigned a0, unsigned a1,
                                         unsigned a2, unsigned a3,
                                         unsigned b0, unsigned b1)
{
    asm("mma.sync.aligned.m16n8k16.row.col.f32.bf16.bf16.f32 "
        "{%0,%1,%2,%3}, {%4,%5,%6,%7}, {%8,%9}, {%0,%1,%2,%3};"
        : "+f"(c[0]), "+f"(c[1]), "+f"(c[2]), "+f"(c[3])
        : "r"(a0), "r"(a1), "r"(a2), "r"(a3), "r"(b0), "r"(b1));
}

__device__ __forceinline__ unsigned pack_bf16x2(float lo, float hi)
{
    __nv_bfloat162 h = __floats2bfloat162_rn(lo, hi);
    return *reinterpret_cast<unsigned*>(&h);
}

__device__ __forceinline__ void cp_async16(unsigned smem_dst, const void* gsrc)
{
    asm volatile("cp.async.cg.shared.global [%0], [%1], 16;"
                 :: "r"(smem_dst), "l"(gsrc));
}
__device__ __forceinline__ void cp_async_wait_all()
{
    asm volatile("cp.async.commit_group;");
    asm volatile("cp.async.wait_group 0;");
}

// ---------------- detect edge_index dtype (int32 vs int64) ------------------
__global__ void detect_kernel(const unsigned* __restrict__ ei, int E)
{
    if (blockIdx.x == 0 && threadIdx.x == 0) {
        int is64 = 1;
        int m = (E >= 64) ? 64 : E;
        for (int i = 0; i < m; i++) {
            if (ei[2 * i + 1] != 0u) { is64 = 0; break; }
        }
        g_is64 = is64;
    }
}

// ---------------- weight pre-conversion to bf16x2 ----------------------------
// layout: [j][kp], kp = k/2, 64 u32 per row.
__global__ void wprep_kernel(const float* __restrict__ Wq,
                             const float* __restrict__ Wk,
                             const float* __restrict__ Wv,
                             const float* __restrict__ Wo)
{
    int i = blockIdx.x * blockDim.x + threadIdx.x;   // over 128*64
    if (i < DMODEL * 64) {
        const float2* q2 = reinterpret_cast<const float2*>(Wq);
        const float2* k2 = reinterpret_cast<const float2*>(Wk);
        const float2* v2 = reinterpret_cast<const float2*>(Wv);
        const float2* o2 = reinterpret_cast<const float2*>(Wo);
        float2 a;
        a = q2[i]; g_Wb32[i]                   = pack_bf16x2(a.x, a.y);
        a = k2[i]; g_Wb32[DMODEL * 64 + i]     = pack_bf16x2(a.x, a.y);
        a = v2[i]; g_Wb32[2 * DMODEL * 64 + i] = pack_bf16x2(a.x, a.y);
        a = o2[i]; g_Wob32[i]                  = pack_bf16x2(a.x, a.y);
    }
}

// ---------------- prep: int32 indices + edge gate + AGG zero -----------------
__global__ void prep_kernel(const void* __restrict__ eiv,
                            const float* __restrict__ eattr,
                            int E, int n4)
{
    const int e = blockIdx.x * blockDim.x + threadIdx.x;
    if (e < E) {
        int row, col;
        if (g_is64) {
            const long long* p = reinterpret_cast<const long long*>(eiv);
            row = (int)p[e];
            col = (int)p[(long long)E + e];
        } else {
            const int* p = reinterpret_cast<const int*>(eiv);
            row = p[e];
            col = p[E + e];
        }
        g_row[e] = row;
        g_col[e] = col;

        const float4* a4 = reinterpret_cast<const float4*>(eattr) + (size_t)e * 4;
        float s = 0.f;
#pragma unroll
        for (int i = 0; i < 4; i++) {
            float4 a = a4[i];
            s += a.x + a.y + a.z + a.w;
        }
        g_ew[e] = 1.f / (1.f + __expf(-s));
    }
    const int total = gridDim.x * blockDim.x;
    float4 z = make_float4(0.f, 0.f, 0.f, 0.f);
    float4* p4 = reinterpret_cast<float4*>(g_AGG);
    for (int i = e; i < n4; i += total) p4[i] = z;
}

// ---------------- fused QKV projection GEMM (bf16 MMA, bf16 out) ------------
// grid (nrb, 2): block = 128 rows x one 64-col half of all 3 weights.
// Tiles: bf16x2-packed u32, 64 u32/row, stride TSTRIDE=68.
// 8 warps as 4x2 over (128 rows x 64 cols); m16n8k16 => 8 k-tiles.
#define QKV_SMEM ((128 * TSTRIDE + 64 * TSTRIDE) * 4)

__global__ void __launch_bounds__(256, 3)
qkv_kernel(const float* __restrict__ x, int n)
{
    extern __shared__ unsigned smu[];
    unsigned* xs = smu;                   // [128][68] bf16x2 (64 used)
    unsigned* ws = smu + 128 * TSTRIDE;   // [64][68]  bf16x2

    const int row0 = blockIdx.x * 128;
    const int h    = blockIdx.y;         // column half
    const int tid  = threadIdx.x;
    const int warp = tid >> 5;
    const int lane = tid & 31;
    const int g    = lane >> 2;
    const int tg   = lane & 3;
    const int rb   = (warp & 3) * 32;
    const int cb   = (warp >> 2) * 32;

    const unsigned ws_base = (unsigned)__cvta_generic_to_shared(ws);

    // load x tile once, convert fp32 -> bf16x2 (64 u32 per row)
    for (int t = tid; t < 128 * 32; t += 256) {
        int r  = t >> 5;
        int c4 = t & 31;                 // float4 chunk: 4 floats -> 2 u32
        float4 v = make_float4(0.f, 0.f, 0.f, 0.f);
        int gr = row0 + r;
        if (gr < n) v = reinterpret_cast<const float4*>(x)[gr * 32 + c4];
        unsigned u0 = pack_bf16x2(v.x, v.y);
        unsigned u1 = pack_bf16x2(v.z, v.w);
        unsigned long long u64v =
            (unsigned long long)u0 | ((unsigned long long)u1 << 32);
        *reinterpret_cast<unsigned long long*>(xs + r * TSTRIDE + c4 * 2) = u64v;
    }

    __nv_bfloat16* Os[3] = {g_Qh, g_Kh, g_Vh};

    for (int w = 0; w < 3; w++) {
        __syncthreads();  // xs ready (w=0) / prior MMA done with ws
        // copy pre-converted weight half rows [h*64, h*64+64): 64 rows x 64 u32
        const unsigned* Wsrc = g_Wb32 + (w * DMODEL + h * 64) * 64;
        for (int t = tid; t < 64 * 16; t += 256) {
            int r   = t >> 4;
            int c16 = t & 15;            // 16 chunks x 4 u32 = 64 u32
            cp_async16(ws_base + (r * TSTRIDE + c16 * 4) * 4,
                       Wsrc + r * 64 + c16 * 4);
        }
        cp_async_wait_all();
        __syncthreads();

        float c[2][4][4];
#pragma unroll
        for (int mt = 0; mt < 2; mt++)
#pragma unroll
            for (int nt = 0; nt < 4; nt++)
#pragma unroll
                for (int i = 0; i < 4; i++) c[mt][nt][i] = 0.f;

#pragma unroll
        for (int kt = 0; kt < 8; kt++) {
            const int kp0 = kt * 8;   // pair base (16 k values per tile)
            unsigned a[2][4];
#pragma unroll
            for (int mt = 0; mt < 2; mt++) {
                int r = rb + mt * 16 + g;
                a[mt][0] = xs[r * TSTRIDE + kp0 + tg];
                a[mt][1] = xs[(r + 8) * TSTRIDE + kp0 + tg];
                a[mt][2] = xs[r * TSTRIDE + kp0 + tg + 4];
                a[mt][3] = xs[(r + 8) * TSTRIDE + kp0 + tg + 4];
            }
#pragma unroll
            for (int nt = 0; nt < 4; nt++) {
                int jn = cb + nt * 8 + g;
                unsigned b0 = ws[jn * TSTRIDE + kp0 + tg];
                unsigned b1 = ws[jn * TSTRIDE + kp0 + tg + 4];
                mma_bf16(c[0][nt], a[0][0], a[0][1], a[0][2], a[0][3], b0, b1);
                mma_bf16(c[1][nt], a[1][0], a[1][1], a[1][2], a[1][3], b0, b1);
            }
        }

        const float scale = (w == 0) ? 0.25f : 1.0f;  // fold 1/sqrt(HD) into Q
        __nv_bfloat162* OUT = reinterpret_cast<__nv_bfloat162*>(Os[w]);
#pragma unroll
        for (int mt = 0; mt < 2; mt++) {
#pragma unroll
            for (int nt = 0; nt < 4; nt++) {
                int cp = (h * 64 + cb + nt * 8 + 2 * tg) >> 1;
                int r1 = row0 + rb + mt * 16 + g;
                int r2 = r1 + 8;
                if (r1 < n)
                    OUT[r1 * 64 + cp] = __floats2bfloat162_rn(
                        c[mt][nt][0] * scale, c[mt][nt][1] * scale);
                if (r2 < n)
                    OUT[r2 * 64 + cp] = __floats2bfloat162_rn(
                        c[mt][nt][2] * scale, c[mt][nt][3] * scale);
            }
        }
    }
}

// ---------------- per-edge attention + scatter-add --------------------------
// One warp handles TWO edges (half-warp each). Lane hl (0..15) owns 8 floats
// [8hl..8hl+7] via one uint4 (LDG.128). head = hl>>1; softmax over heads via
// xor {2,4,8} (confined to the half-warp).
__global__ void __launch_bounds__(256)
edge_kernel(int E)
{
    const int gw   = (blockIdx.x * blockDim.x + threadIdx.x) >> 5;
    const int lane = threadIdx.x & 31;
    const int hw   = lane >> 4;
    const int hl   = lane & 15;

    long long e0 = (long long)gw * 2;
    if (e0 >= E) return;
    long long el = e0 + hw;
    const int active = (el < E);
    const int e = active ? (int)el : (int)e0;

    const int row = __ldg(&g_row[e]);
    const int col = __ldg(&g_col[e]);
    float ew = __ldg(&g_ew[e]);

    const uint4* Q4 = reinterpret_cast<const uint4*>(g_Qh);
    const uint4* K4 = reinterpret_cast<const uint4*>(g_Kh);
    const uint4* V4 = reinterpret_cast<const uint4*>(g_Vh);

    uint4 qu = Q4[row * 16 + hl];
    uint4 ku = K4[col * 16 + hl];
    uint4 vu = V4[row * 16 + hl];

    float2 q0 = __bfloat1622float2(*reinterpret_cast<__nv_bfloat162*>(&qu.x));
    float2 q1 = __bfloat1622float2(*reinterpret_cast<__nv_bfloat162*>(&qu.y));
    float2 q2 = __bfloat1622float2(*reinterpret_cast<__nv_bfloat162*>(&qu.z));
    float2 q3 = __bfloat1622float2(*reinterpret_cast<__nv_bfloat162*>(&qu.w));
    float2 k0 = __bfloat1622float2(*reinterpret_cast<__nv_bfloat162*>(&ku.x));
    float2 k1 = __bfloat1622float2(*reinterpret_cast<__nv_bfloat162*>(&ku.y));
    float2 k2 = __bfloat1622float2(*reinterpret_cast<__nv_bfloat162*>(&ku.z));
    float2 k3 = __bfloat1622float2(*reinterpret_cast<__nv_bfloat162*>(&ku.w));
    float2 v0 = __bfloat1622float2(*reinterpret_cast<__nv_bfloat162*>(&vu.x));
    float2 v1 = __bfloat1622float2(*reinterpret_cast<__nv_bfloat162*>(&vu.y));
    float2 v2 = __bfloat1622float2(*reinterpret_cast<__nv_bfloat162*>(&vu.z));
    float2 v3 = __bfloat1622float2(*reinterpret_cast<__nv_bfloat162*>(&vu.w));

    // per-head dot: 8 products per lane, + partner lane (xor 1) = HD=16
    float s = q0.x * k0.x + q0.y * k0.y + q1.x * k1.x + q1.y * k1.y +
              q2.x * k2.x + q2.y * k2.y + q3.x * k3.x + q3.y * k3.y;
    s += __shfl_xor_sync(0xffffffffu, s, 1);
    s = (s > 0.f) ? s : ALPHA * s;
    s *= ew;

    // softmax across 8 heads (lane bits 1..3)
    float m = s;
    m = fmaxf(m, __shfl_xor_sync(0xffffffffu, m, 2));
    m = fmaxf(m, __shfl_xor_sync(0xffffffffu, m, 4));
    m = fmaxf(m, __shfl_xor_sync(0xffffffffu, m, 8));
    float p = __expf(s - m);
    float den = p;
    den += __shfl_xor_sync(0xffffffffu, den, 2);
    den += __shfl_xor_sync(0xffffffffu, den, 4);
    den += __shfl_xor_sync(0xffffffffu, den, 8);
    p /= den;

    if (active) {
        float* dst = g_AGG + (size_t)col * DMODEL + hl * 8;
        asm volatile("red.global.add.v4.f32 [%0], {%1, %2, %3, %4};"
                     :: "l"(dst), "f"(p * v0.x), "f"(p * v0.y),
                        "f"(p * v1.x), "f"(p * v1.y)
                     : "memory");
        asm volatile("red.global.add.v4.f32 [%0], {%1, %2, %3, %4};"
                     :: "l"(dst + 4), "f"(p * v2.x), "f"(p * v2.y),
                        "f"(p * v3.x), "f"(p * v3.y)
                     : "memory");
    }
}

// ---------------- output projection + residual + LayerNorm (bf16 MMA) -------
// AGG converted to bf16x2 tiles; MMA as in qkv (both halves accumulated),
// result staged to fp32 res[128][132] aliasing the tiles, then LN.
#define OUT_SMEM (128 * 132 * 4)

__global__ void __launch_bounds__(256, 2)
out_ln_kernel(const float* __restrict__ x,
              const float* __restrict__ bo,
              const float* __restrict__ gamma,
              const float* __restrict__ beta,
              float* __restrict__ out,
              int n)
{
    extern __shared__ unsigned smu[];
    unsigned* as = smu;                   // [128][68] bf16x2 AGG
    unsigned* ws = smu + 128 * TSTRIDE;   // [64][68]  bf16x2 Wo half
    float* res = reinterpret_cast<float*>(smu);  // [128][132] fp32 (aliases)

    const int row0 = blockIdx.x * 128;
    const int tid  = threadIdx.x;
    const int warp = tid >> 5;
    const int lane = tid & 31;
    const int g    = lane >> 2;
    const int tg   = lane & 3;
    const int rb   = (warp & 3) * 32;
    const int cb   = (warp >> 2) * 32;

    const unsigned ws_base = (unsigned)__cvta_generic_to_shared(ws);

    for (int t = tid; t < 128 * 32; t += 256) {
        int r  = t >> 5;
        int c4 = t & 31;
        float4 v = make_float4(0.f, 0.f, 0.f, 0.f);
        int gr = row0 + r;
        if (gr < n) v = reinterpret_cast<const float4*>(g_AGG)[gr * 32 + c4];
        unsigned u0 = pack_bf16x2(v.x, v.y);
        unsigned u1 = pack_bf16x2(v.z, v.w);
        unsigned long long u64v =
            (unsigned long long)u0 | ((unsigned long long)u1 << 32);
        *reinterpret_cast<unsigned long long*>(as + r * TSTRIDE + c4 * 2) = u64v;
    }

    float c[2][2][4][4];   // [half][mt][nt][i]
#pragma unroll
    for (int h = 0; h < 2; h++)
#pragma unroll
        for (int mt = 0; mt < 2; mt++)
#pragma unroll
            for (int nt = 0; nt < 4; nt++)
#pragma unroll
                for (int i = 0; i < 4; i++) c[h][mt][nt][i] = 0.f;

    for (int h = 0; h < 2; h++) {
        __syncthreads();
        const unsigned* Wsrc = g_Wob32 + (h * 64) * 64;
        for (int t = tid; t < 64 * 16; t += 256) {
            int r   = t >> 4;
            int c16 = t & 15;
            cp_async16(ws_base + (r * TSTRIDE + c16 * 4) * 4,
                       Wsrc + r * 64 + c16 * 4);
        }
        cp_async_wait_all();
        __syncthreads();

#pragma unroll
        for (int kt = 0; kt < 8; kt++) {
            const int kp0 = kt * 8;
            unsigned a[2][4];
#pragma unroll
            for (int mt = 0; mt < 2; mt++) {
                int r = rb + mt * 16 + g;
                a[mt][0] = as[r * TSTRIDE + kp0 + tg];
                a[mt][1] = as[(r + 8) * TSTRIDE + kp0 + tg];
                a[mt][2] = as[r * TSTRIDE + kp0 + tg + 4];
                a[mt][3] = as[(r + 8) * TSTRIDE + kp0 + tg + 4];
            }
#pragma unroll
            for (int nt = 0; nt < 4; nt++) {
                int jn = cb + nt * 8 + g;
                unsigned b0 = ws[jn * TSTRIDE + kp0 + tg];
                unsigned b1 = ws[jn * TSTRIDE + kp0 + tg + 4];
                mma_bf16(c[h][0][nt], a[0][0], a[0][1], a[0][2], a[0][3], b0, b1);
                mma_bf16(c[h][1][nt], a[1][0], a[1][1], a[1][2], a[1][3], b0, b1);
            }
        }
    }

    __syncthreads();  // all MMAs done with as/ws; overwrite with fp32 staging
#pragma unroll
    for (int h = 0; h < 2; h++)
#pragma unroll
        for (int mt = 0; mt < 2; mt++)
#pragma unroll
            for (int nt = 0; nt < 4; nt++) {
                int r1 = rb + mt * 16 + g;
                int cc = h * 64 + cb + nt * 8 + 2 * tg;
                res[r1 * 132 + cc]           = c[h][mt][nt][0];
                res[r1 * 132 + cc + 1]       = c[h][mt][nt][1];
                res[(r1 + 8) * 132 + cc]     = c[h][mt][nt][2];
                res[(r1 + 8) * 132 + cc + 1] = c[h][mt][nt][3];
            }
    __syncthreads();

    float4 bo4 = reinterpret_cast<const float4*>(bo)[lane];
    float4 g4  = reinterpret_cast<const float4*>(gamma)[lane];
    float4 b4  = reinterpret_cast<const float4*>(beta)[lane];

    for (int r = warp; r < 128; r += 8) {
        int gr = row0 + r;
        if (gr >= n) continue;
        float4 a  = *reinterpret_cast<float4*>(res + r * 132 + lane * 4);
        float4 xv = reinterpret_cast<const float4*>(x)[gr * 32 + lane];
        float o0 = a.x + bo4.x + xv.x;
        float o1 = a.y + bo4.y + xv.y;
        float o2 = a.z + bo4.z + xv.z;
        float o3 = a.w + bo4.w + xv.w;

        float s  = o0 + o1 + o2 + o3;
        float ss = o0 * o0 + o1 * o1 + o2 * o2 + o3 * o3;
#pragma unroll
        for (int off = 16; off >= 1; off >>= 1) {
            s  += __shfl_xor_sync(0xffffffffu, s,  off);
            ss += __shfl_xor_sync(0xffffffffu, ss, off);
        }
        float mu  = s * (1.f / 128.f);
        float var = ss * (1.f / 128.f) - mu * mu;
        float inv = rsqrtf(var + LN_EPS);

        float4 o;
        o.x = (o0 - mu) * inv * g4.x + b4.x;
        o.y = (o1 - mu) * inv * g4.y + b4.y;
        o.z = (o2 - mu) * inv * g4.z + b4.z;
        o.w = (o3 - mu) * inv * g4.w + b4.w;
        reinterpret_cast<float4*>(out)[gr * 32 + lane] = o;
    }
}

// ---------------- launcher ---------------------------------------------------
extern "C" void kernel_launch(void* const* d_in, const int* in_sizes, int n_in,
                              void* d_out, int out_size)
{
    const float* x     = (const float*)d_in[0];
    const void*  ei    = d_in[1];
    const float* eattr = (const float*)d_in[2];
    const float* Wq    = (const float*)d_in[3];
    const float* Wk    = (const float*)d_in[4];
    const float* Wv    = (const float*)d_in[5];
    const float* Wo    = (const float*)d_in[6];
    const float* bo    = (const float*)d_in[7];
    const float* gamma = (const float*)d_in[8];
    const float* beta  = (const float*)d_in[9];
    float* out = (float*)d_out;

    int n = in_sizes[0] / DMODEL;
    int E = in_sizes[1] / 2;
    if (n > NMAX) n = NMAX;

    cudaFuncSetAttribute(qkv_kernel,
                         cudaFuncAttributeMaxDynamicSharedMemorySize, QKV_SMEM);
    cudaFuncSetAttribute(out_ln_kernel,
                         cudaFuncAttributeMaxDynamicSharedMemorySize, OUT_SMEM);

    detect_kernel<<<1, 32>>>((const unsigned*)ei, E);
    wprep_kernel<<<(DMODEL * 64 + 255) / 256, 256>>>(Wq, Wk, Wv, Wo);
    prep_kernel<<<(E + 255) / 256, 256>>>(ei, eattr, E, n * 32);

    int nrb = (n + 127) / 128;
    qkv_kernel<<<dim3(nrb, 2), 256, QKV_SMEM>>>(x, n);

    long long nwarps = ((long long)E + 1) / 2;
    int eblocks = (int)((nwarps + 7) / 8);   // 8 warps (256 threads) per block
    edge_kernel<<<eblocks, 256>>>(E);

    out_ln_kernel<<<nrb, 256, OUT_SMEM>>>(x, bo, gamma, beta, out, n);
}